// round 2
// baseline (speedup 1.0000x reference)
#include <cuda_runtime.h>

// out = x^2 * 0.1 over N fp32 elements. Pure HBM-bound streaming kernel.
// float4 vectorization, grid-stride loop.

__global__ void __launch_bounds__(256) poly_kernel_v4(const float4* __restrict__ x,
                                                      float4* __restrict__ out,
                                                      int n4) {
    int stride = gridDim.x * blockDim.x;
    for (int i = blockIdx.x * blockDim.x + threadIdx.x; i < n4; i += stride) {
        float4 v = x[i];
        float4 r;
        r.x = v.x * v.x * 0.1f;
        r.y = v.y * v.y * 0.1f;
        r.z = v.z * v.z * 0.1f;
        r.w = v.w * v.w * 0.1f;
        out[i] = r;
    }
}

// Tail handler for n not divisible by 4 (not needed for 64*1024*1024, but safe).
__global__ void poly_kernel_tail(const float* __restrict__ x,
                                 float* __restrict__ out,
                                 int start, int n) {
    int i = start + blockIdx.x * blockDim.x + threadIdx.x;
    if (i < n) {
        float v = x[i];
        out[i] = v * v * 0.1f;
    }
}

extern "C" void kernel_launch(void* const* d_in, const int* in_sizes, int n_in,
                              void* d_out, int out_size) {
    const float* x = (const float*)d_in[0];
    float* out = (float*)d_out;
    int n = in_sizes[0];

    int n4 = n / 4;
    const int threads = 256;
    // Size grid for ~full chip with a few waves: enough CTAs that each thread
    // processes a handful of float4s, keeping MLP deep via loop unrolling by ptxas.
    int blocks = (n4 + threads - 1) / threads;
    const int max_blocks = 148 * 16;  // cap so the grid-stride loop has iterations
    if (blocks > max_blocks) blocks = max_blocks;

    if (n4 > 0) {
        poly_kernel_v4<<<blocks, threads>>>((const float4*)x, (float4*)out, n4);
    }

    int rem = n - n4 * 4;
    if (rem > 0) {
        poly_kernel_tail<<<1, 256>>>(x, out, n4 * 4, n);
    }
}